// round 1
// baseline (speedup 1.0000x reference)
#include <cuda_runtime.h>

// CondFilterT: per batch row b
//   e = table[input[b,0]]            -> out[b, 0:64] (raw)
//   for c in 0..49:
//     v = table[input[b,1+c]]
//     out[b, 64+c*64 : 64+(c+1)*64] = v * (e_nrm . v) / (v . v)
//
// Shapes: BATCH=16384, NCONDS=50, EMB=64.
// d_in[0] = input  (int32, 16384*51)
// d_in[1] = event_table (float32, 100002*64)
// d_out   = float32, 16384*3264

#define BATCH   16384
#define NCONDS  50
#define EMB     64
#define ROW_IN  (1 + NCONDS)          // 51
#define ROW_OUT ((1 + NCONDS) * EMB)  // 3264

__global__ __launch_bounds__(128, 8)
void cond_filter_kernel(const int* __restrict__ inp,
                        const float* __restrict__ tab,
                        float* __restrict__ out)
{
    const int b    = blockIdx.x;
    const int wid  = threadIdx.x >> 5;
    const int lane = threadIdx.x & 31;

    __shared__ int    s_idx[ROW_IN];
    __shared__ float2 s_enrm[32];   // normalized event embedding, float2 per lane

    // Load this row's 51 indices into shared (coalesced-ish, tiny).
    if (threadIdx.x < ROW_IN)
        s_idx[threadIdx.x] = inp[(size_t)b * ROW_IN + threadIdx.x];
    __syncthreads();

    const float2* __restrict__ tab2 = reinterpret_cast<const float2*>(tab);
    float2* __restrict__ out2 = reinterpret_cast<float2*>(out + (size_t)b * ROW_OUT);

    // Warp 0: event embedding -> raw store + normalized copy in shared.
    if (wid == 0) {
        const int ei = s_idx[0];
        float2 e2 = __ldg(&tab2[(size_t)ei * 32 + lane]);

        // raw event embedding to out[b, 0:64]
        out2[lane] = e2;

        float ss = fmaf(e2.x, e2.x, e2.y * e2.y);
        #pragma unroll
        for (int o = 16; o > 0; o >>= 1)
            ss += __shfl_xor_sync(0xffffffffu, ss, o);

        const float inv = rsqrtf(ss);
        s_enrm[lane] = make_float2(e2.x * inv, e2.y * inv);
    }
    __syncthreads();

    const float2 en = s_enrm[lane];

    // 4 warps stride over the 50 conditions.
    for (int c = wid; c < NCONDS; c += 4) {
        const int ci = s_idx[c + 1];
        float2 v = __ldg(&tab2[(size_t)ci * 32 + lane]);

        float vv = fmaf(v.x, v.x, v.y * v.y);
        float ev = fmaf(en.x, v.x, en.y * v.y);
        #pragma unroll
        for (int o = 16; o > 0; o >>= 1) {
            vv += __shfl_xor_sync(0xffffffffu, vv, o);
            ev += __shfl_xor_sync(0xffffffffu, ev, o);
        }

        const float s = __fdividef(ev, vv);   // (e_nrm.v)/(v.v)
        out2[32 + (size_t)c * 32 + lane] = make_float2(v.x * s, v.y * s);
    }
}

extern "C" void kernel_launch(void* const* d_in, const int* in_sizes, int n_in,
                              void* d_out, int out_size)
{
    const int*   inp = (const int*)d_in[0];
    const float* tab = (const float*)d_in[1];
    float*       out = (float*)d_out;

    (void)in_sizes; (void)n_in; (void)out_size;

    cond_filter_kernel<<<BATCH, 128>>>(inp, tab, out);
}

// round 5
// speedup vs baseline: 1.2495x; 1.2495x over previous
#include <cuda_runtime.h>

// CondFilterT: per batch row b
//   e = table[input[b,0]]            -> out[b, 0:64] (raw)
//   for c in 0..49:
//     v = table[input[b,1+c]]
//     out[b, 64+c*64 : +64] = v * (e_nrm . v) / (v . v)
//
// BATCH=16384, NCONDS=50, EMB=64.
// d_in[0] = input (int32 16384x51), d_in[1] = event_table (fp32 100002x64)
// d_out = fp32 16384x3264

#define BATCH   16384
#define NCONDS  50
#define ROW_IN  51
#define ROW_OUT 3264
#define NGROUPS 8          // half-warp (16-lane) groups per 128-thread CTA
#define ITERS   7          // ceil(50/8)

__device__ __forceinline__ float dot4(float4 a, float4 b) {
    return fmaf(a.x, b.x, fmaf(a.y, b.y, fmaf(a.z, b.z, a.w * b.w)));
}

__global__ __launch_bounds__(128, 8)
void cond_filter_kernel(const int* __restrict__ inp,
                        const float* __restrict__ tab,
                        float* __restrict__ out)
{
    const int b     = blockIdx.x;
    const int tid   = threadIdx.x;
    const int wid   = tid >> 5;
    const int lane  = tid & 31;
    const int group = tid >> 4;     // 0..7
    const int gl    = tid & 15;     // lane within 16-lane group

    __shared__ int s_idx[ROW_IN];

    if (tid < ROW_IN)
        s_idx[tid] = inp[(size_t)b * ROW_IN + tid];
    __syncthreads();

    const float4* __restrict__ tab4 = reinterpret_cast<const float4*>(tab);
    float4* __restrict__ out4 = reinterpret_cast<float4*>(out + (size_t)b * ROW_OUT);

    // ---- Front-batch all gathers for this group (MLP) ----
    int   ci[ITERS];
    float4 v[ITERS];
    #pragma unroll
    for (int i = 0; i < ITERS; i++) {
        const int c = group + NGROUPS * i;
        ci[i] = (c < NCONDS) ? s_idx[c + 1] : s_idx[0];
    }
    #pragma unroll
    for (int i = 0; i < ITERS; i++)
        v[i] = __ldg(&tab4[(size_t)ci[i] * 16 + gl]);

    // ---- Event embedding: each warp computes e_nrm redundantly ----
    // lanes 16-31 load the same addresses as 0-15 (warp-broadcast, L1 hit)
    const int ei = s_idx[0];
    const float4 e4 = __ldg(&tab4[(size_t)ei * 16 + gl]);

    if (wid == 0 && lane < 16)
        out4[gl] = e4;   // raw event embedding -> out[b, 0:64]

    float ss = dot4(e4, e4);
    #pragma unroll
    for (int o = 8; o > 0; o >>= 1)
        ss += __shfl_xor_sync(0xffffffffu, ss, o);
    const float inv = rsqrtf(ss);
    const float4 en = make_float4(e4.x * inv, e4.y * inv, e4.z * inv, e4.w * inv);

    // ---- Reduce + scale + store, 2 conditions per warp per iteration ----
    #pragma unroll
    for (int i = 0; i < ITERS; i++) {
        const int c = group + NGROUPS * i;
        float vv = dot4(v[i], v[i]);
        float ev = dot4(en, v[i]);
        #pragma unroll
        for (int o = 8; o > 0; o >>= 1) {
            vv += __shfl_xor_sync(0xffffffffu, vv, o);
            ev += __shfl_xor_sync(0xffffffffu, ev, o);
        }
        if (c < NCONDS) {
            const float s = __fdividef(ev, vv);
            out4[16 + (size_t)c * 16 + gl] =
                make_float4(v[i].x * s, v[i].y * s, v[i].z * s, v[i].w * s);
        }
    }
}

extern "C" void kernel_launch(void* const* d_in, const int* in_sizes, int n_in,
                              void* d_out, int out_size)
{
    const int*   inp = (const int*)d_in[0];
    const float* tab = (const float*)d_in[1];
    float*       out = (float*)d_out;
    (void)in_sizes; (void)n_in; (void)out_size;

    cond_filter_kernel<<<BATCH, 128>>>(inp, tab, out);
}

// round 6
// speedup vs baseline: 1.3706x; 1.0969x over previous
#include <cuda_runtime.h>

// CondFilterT: per batch row b
//   e = table[input[b,0]]            -> out[b, 0:64] (raw)
//   for c in 0..49:
//     v = table[input[b,1+c]]
//     out[b, 64+c*64 : +64] = v * (e_nrm . v) / (v . v)
//
// BATCH=16384, NCONDS=50, EMB=64.
// d_in[0] = input (int32 16384x51), d_in[1] = event_table (fp32 100002x64)
// d_out = fp32 16384x3264

#define BATCH   16384
#define NCONDS  50
#define ROW_IN  51
#define ROW_OUT 3264
#define NGROUPS 8          // 16-lane groups per 128-thread CTA

__device__ __forceinline__ float dot4(float4 a, float4 b) {
    return fmaf(a.x, b.x, fmaf(a.y, b.y, fmaf(a.z, b.z, a.w * b.w)));
}

__global__ __launch_bounds__(128, 12)
void cond_filter_kernel(const int* __restrict__ inp,
                        const float* __restrict__ tab,
                        float* __restrict__ out)
{
    const int b     = blockIdx.x;
    const int tid   = threadIdx.x;
    const int group = tid >> 4;     // 0..7
    const int gl    = tid & 15;     // lane in 16-lane group

    __shared__ int s_idx[ROW_IN];

    if (tid < ROW_IN)
        s_idx[tid] = inp[(size_t)b * ROW_IN + tid];
    __syncthreads();

    const float4* __restrict__ tab4 = reinterpret_cast<const float4*>(tab);
    float4* __restrict__ out4 = reinterpret_cast<float4*>(out + (size_t)b * ROW_OUT);

    // ---- Event embedding (every warp, broadcast loads -> L1 hits) ----
    const float4 e4 = __ldg(&tab4[(size_t)s_idx[0] * 16 + gl]);
    if (tid < 16)
        out4[gl] = e4;   // raw event embedding -> out[b, 0:64]

    float ss = dot4(e4, e4);
    #pragma unroll
    for (int o = 8; o > 0; o >>= 1)
        ss += __shfl_xor_sync(0xffffffffu, ss, o);
    const float inv = rsqrtf(ss);
    const float4 en = make_float4(e4.x * inv, e4.y * inv, e4.z * inv, e4.w * inv);

    // ==== Chunk A: conds group + 8*{0,1,2,3} (always < 50) ====
    {
        float4 v[4];
        #pragma unroll
        for (int i = 0; i < 4; i++) {
            const int ci = s_idx[1 + group + NGROUPS * i];
            v[i] = __ldg(&tab4[(size_t)ci * 16 + gl]);
        }
        #pragma unroll
        for (int i = 0; i < 4; i++) {
            float vv = dot4(v[i], v[i]);
            float ev = dot4(en, v[i]);
            #pragma unroll
            for (int o = 8; o > 0; o >>= 1) {
                vv += __shfl_xor_sync(0xffffffffu, vv, o);
                ev += __shfl_xor_sync(0xffffffffu, ev, o);
            }
            const float s = __fdividef(ev, vv);
            const int c = group + NGROUPS * i;
            out4[16 + (size_t)c * 16 + gl] =
                make_float4(v[i].x * s, v[i].y * s, v[i].z * s, v[i].w * s);
        }
    }

    // ==== Chunk B: conds group+32, group+40 (always valid), group+48 (groups 0,1) ====
    {
        const bool has3 = (group + 48) < NCONDS;   // groups 0,1 only
        float4 v[3];
        #pragma unroll
        for (int i = 0; i < 3; i++) {
            const int c  = group + 32 + NGROUPS * i;
            const int ci = (i < 2 || has3) ? s_idx[1 + c] : s_idx[0];
            v[i] = __ldg(&tab4[(size_t)ci * 16 + gl]);
        }
        #pragma unroll
        for (int i = 0; i < 3; i++) {
            float vv = dot4(v[i], v[i]);
            float ev = dot4(en, v[i]);
            #pragma unroll
            for (int o = 8; o > 0; o >>= 1) {
                vv += __shfl_xor_sync(0xffffffffu, vv, o);
                ev += __shfl_xor_sync(0xffffffffu, ev, o);
            }
            if (i < 2 || has3) {
                const float s = __fdividef(ev, vv);
                const int c = group + 32 + NGROUPS * i;
                out4[16 + (size_t)c * 16 + gl] =
                    make_float4(v[i].x * s, v[i].y * s, v[i].z * s, v[i].w * s);
            }
        }
    }
}

extern "C" void kernel_launch(void* const* d_in, const int* in_sizes, int n_in,
                              void* d_out, int out_size)
{
    const int*   inp = (const int*)d_in[0];
    const float* tab = (const float*)d_in[1];
    float*       out = (float*)d_out;
    (void)in_sizes; (void)n_in; (void)out_size;

    cond_filter_kernel<<<BATCH, 128>>>(inp, tab, out);
}